// round 16
// baseline (speedup 1.0000x reference)
#include <cuda_runtime.h>
#include <cuda_fp16.h>
#include <math.h>
#include <stdint.h>

#define NN 262144
#define DD 256
#define DOUT 128
#define SEGS 4096

// ---------------- device scratch (no allocations allowed) -------------------
__device__ __half g_s16[(size_t)NN * DD];   // scores s as fp16
__device__ __half g_x16[(size_t)NN * DD];   // x as fp16 (side product of MLP)
__device__ float g_sx[SEGS * DD];           // segment-weighted sums
__device__ int   g_offs[SEGS + 1];          // segment start offsets
// pre-transposed fp16 weights, layout [n][k] (K contiguous, K=256)
__device__ __half g_w1t[DD * DD], g_w2t[DD * DD];
__device__ __half g_w3t[DD * DD], g_w4t[DOUT * DD];

// ---------------- helpers ---------------------------------------------------
__device__ __forceinline__ uint32_t smem_u32(const void* p) {
    uint32_t a;
    asm("{ .reg .u64 t; cvta.to.shared.u64 t, %1; cvt.u32.u64 %0, t; }"
        : "=r"(a) : "l"(p));
    return a;
}

__device__ __forceinline__ void ldm_x4(uint32_t* r, uint32_t addr) {
    asm volatile("ldmatrix.sync.aligned.m8n8.x4.shared.b16 {%0,%1,%2,%3}, [%4];"
                 : "=r"(r[0]), "=r"(r[1]), "=r"(r[2]), "=r"(r[3]) : "r"(addr));
}

__device__ __forceinline__ void mma16816(float* c, const uint32_t* a,
                                         uint32_t b0, uint32_t b1) {
    asm volatile(
        "mma.sync.aligned.m16n8k16.row.col.f32.f16.f16.f32 "
        "{%0,%1,%2,%3}, {%4,%5,%6,%7}, {%8,%9}, {%0,%1,%2,%3};"
        : "+f"(c[0]), "+f"(c[1]), "+f"(c[2]), "+f"(c[3])
        : "r"(a[0]), "r"(a[1]), "r"(a[2]), "r"(a[3]), "r"(b0), "r"(b1));
}

__device__ __forceinline__ uint32_t pack_f16x2(float x, float y) {
    __half2 h = __floats2half2_rn(x, y);
    return *reinterpret_cast<uint32_t*>(&h);
}

#define CP_ASYNC16(dst, src) \
    asm volatile("cp.async.cg.shared.global [%0], [%1], 16;" \
                 :: "r"(dst), "l"(src) : "memory")
#define CP_COMMIT() asm volatile("cp.async.commit_group;" ::: "memory")
#define CP_WAIT(n)  asm volatile("cp.async.wait_group %0;" :: "n"(n) : "memory")

// ---------------------------------------------------------------------------
// Weight prep: transpose to [n][k] fp16
// ---------------------------------------------------------------------------
__global__ void prep_weights_kernel(const float* __restrict__ W1,
                                    const float* __restrict__ W2,
                                    const float* __restrict__ W3,
                                    const float* __restrict__ W4)
{
    int n = blockIdx.x;
    int k = threadIdx.x;
    int which = blockIdx.y;
    const float* W;
    __half* Wt;
    int ncols;
    if (which == 0)      { W = W1; Wt = g_w1t; ncols = DD; }
    else if (which == 1) { W = W2; Wt = g_w2t; ncols = DD; }
    else if (which == 2) { W = W3; Wt = g_w3t; ncols = DD; }
    else                 { W = W4; Wt = g_w4t; ncols = DOUT; }
    if (n >= ncols) return;
    Wt[n * DD + k] = __float2half_rn(W[k * ncols + n]);
}

__global__ void seg_offsets_kernel(const int* __restrict__ index, int* __restrict__ offs)
{
    int b = blockIdx.x * blockDim.x + threadIdx.x;
    if (b > SEGS) return;
    int lo = 0, hi = NN;
    while (lo < hi) {
        int mid = (lo + hi) >> 1;
        if (index[mid] < b) lo = mid + 1;
        else hi = mid;
    }
    offs[b] = lo;
}

// ---------------------------------------------------------------------------
// Fused 2-layer MLP: out = (silu(A@Wa^T + ba)) @ Wb^T + bb
//  Phase 1: per 128-col half, pipelined fp32->fp16 A + W tiles -> h in SMEM.
//           On nh=0, optionally (X16OUT) write converted A to g_x16.
//  Phase 2: A = h (smem direct), 4-deep W-only cp.async ring.
// ---------------------------------------------------------------------------
#define NC    8
#define PADK  40
#define PADH  264
#define P1STG 20480
#define P2STG 10240
#define OHB   40960
#define SMEM_FUSED (OHB + 128 * PADH * 2)   // 108544 bytes

template <int N2H, bool SOUT, bool X16OUT>
__global__ __launch_bounds__(256, 2)
void fused_mlp(const float* __restrict__ A32,
               const __half* __restrict__ Wa,
               const float* __restrict__ ba,
               const __half* __restrict__ Wb,
               const float* __restrict__ bb,
               __half* __restrict__ S16,
               float* __restrict__ Fout, int ldout,
               __half* __restrict__ X16)
{
    extern __shared__ char dsm[];
    const uint32_t sb = smem_u32(dsm);

    const int tid  = threadIdx.x;
    const int lane = tid & 31;
    const int wid  = tid >> 5;
    const int wm   = wid & 3;
    const int wn   = wid >> 2;
    const int mtile = blockIdx.x * 128;

    const int a_row = (lane & 15);
    const int a_ko  = (lane & 16) ? 8 : 0;
    const int b_row = (lane & 7) + ((lane & 16) ? 8 : 0);
    const int b_ko  = (lane & 8) ? 8 : 0;
    const int gq    = lane >> 2;
    const int tc2   = (lane & 3) * 2;

    float acc[2][8][4];
    float4 ra[4];

    auto zacc = [&] {
#pragma unroll
        for (int i = 0; i < 2; i++)
#pragma unroll
            for (int j = 0; j < 8; j++)
#pragma unroll
                for (int q = 0; q < 4; q++) acc[i][j][q] = 0.0f;
    };
    auto ldgA = [&](int kc) {
        const int k0 = kc * 32;
#pragma unroll
        for (int t = 0; t < 4; t++) {
            int idx = tid + t * 256;
            int r = idx >> 3, c = idx & 7;
            ra[t] = *reinterpret_cast<const float4*>(
                &A32[(size_t)(mtile + r) * DD + k0 + c * 4]);
        }
    };
    auto stcvA = [&](uint32_t stgoff, int kc, bool wout) {
        const int k0 = kc * 32;
#pragma unroll
        for (int t = 0; t < 4; t++) {
            int idx = tid + t * 256;
            int r = idx >> 3, c = idx & 7;
            float4 v = ra[t];
            uint2 p;
            p.x = pack_f16x2(v.x, v.y);
            p.y = pack_f16x2(v.z, v.w);
            *reinterpret_cast<uint2*>(
                dsm + stgoff + (uint32_t)(r * PADK + c * 4) * 2) = p;
            if (X16OUT && wout) {
                *reinterpret_cast<uint2*>(
                    &X16[(size_t)(mtile + r) * DD + k0 + c * 4]) = p;
            }
        }
    };
    auto cpB1 = [&](const __half* Wh, int kc, uint32_t stg) {
        const int k0 = kc * 32;
#pragma unroll
        for (int t = 0; t < 2; t++) {
            int idx = tid + t * 256;
            int r = idx >> 2, c = idx & 3;
            CP_ASYNC16(stg + 10240 + (uint32_t)(r * PADK + c * 8) * 2,
                       Wh + (size_t)r * DD + k0 + c * 8);
        }
    };
    auto cpB2 = [&](const __half* Wh, int kc, uint32_t stg) {
        const int k0 = kc * 32;
#pragma unroll
        for (int t = 0; t < 2; t++) {
            int idx = tid + t * 256;
            int r = idx >> 2, c = idx & 3;
            CP_ASYNC16(stg + (uint32_t)(r * PADK + c * 8) * 2,
                       Wh + (size_t)r * DD + k0 + c * 8);
        }
    };
    auto compute1 = [&](uint32_t stg) {
        const uint32_t bA = stg, bB = stg + 10240;
#pragma unroll
        for (int ks = 0; ks < 2; ks++) {
            const int kb = ks * 16;
            uint32_t a[2][4];
#pragma unroll
            for (int mb = 0; mb < 2; mb++) {
                int row = wm * 32 + mb * 16 + a_row;
                ldm_x4(a[mb], bA + (uint32_t)(row * PADK + kb + a_ko) * 2);
            }
#pragma unroll
            for (int g = 0; g < 4; g++) {
                int n = wn * 64 + g * 16 + b_row;
                uint32_t bh[4];
                ldm_x4(bh, bB + (uint32_t)(n * PADK + kb + b_ko) * 2);
#pragma unroll
                for (int mb = 0; mb < 2; mb++)
#pragma unroll
                    for (int nb = 0; nb < 2; nb++)
                        mma16816(acc[mb][g * 2 + nb], a[mb],
                                 bh[nb * 2], bh[nb * 2 + 1]);
            }
        }
    };
    auto compute2 = [&](uint32_t bstg, int kc) {
#pragma unroll
        for (int ks = 0; ks < 2; ks++) {
            const int kb = ks * 16;
            uint32_t a[2][4];
#pragma unroll
            for (int mb = 0; mb < 2; mb++) {
                int row = wm * 32 + mb * 16 + a_row;
                ldm_x4(a[mb], sb + OHB +
                       (uint32_t)(row * PADH + kc * 32 + kb + a_ko) * 2);
            }
#pragma unroll
            for (int g = 0; g < 4; g++) {
                int n = wn * 64 + g * 16 + b_row;
                uint32_t bh[4];
                ldm_x4(bh, bstg + (uint32_t)(n * PADK + kb + b_ko) * 2);
#pragma unroll
                for (int mb = 0; mb < 2; mb++)
#pragma unroll
                    for (int nb = 0; nb < 2; nb++)
                        mma16816(acc[mb][g * 2 + nb], a[mb],
                                 bh[nb * 2], bh[nb * 2 + 1]);
            }
        }
    };

    // ================= phase 1: h = silu(A@Wa^T + ba) -> HBUF ===============
    const uint32_t p1s[2] = {sb, sb + P1STG};
    for (int nh = 0; nh < 2; nh++) {
        zacc();
        const __half* Wh = Wa + (size_t)nh * 128 * DD;
        const bool wout = (nh == 0);

        ldgA(0); stcvA(0, 0, wout);
        cpB1(Wh, 0, p1s[0]); CP_COMMIT();
        ldgA(1);
        CP_WAIT(0);
        __syncthreads();

#pragma unroll
        for (int kc = 0; kc < NC; kc++) {
            const uint32_t cur = p1s[kc & 1];
            const uint32_t nxt = p1s[(kc + 1) & 1];
            if (kc + 1 < NC) {
                stcvA(nxt - sb, kc + 1, wout);
                if (kc + 2 < NC) ldgA(kc + 2);
                cpB1(Wh, kc + 1, nxt); CP_COMMIT();
            }
            compute1(cur);
            CP_WAIT(0);
            __syncthreads();
        }

        // epilogue: silu -> h buffer (fp16, local rows)
#pragma unroll
        for (int mb = 0; mb < 2; mb++) {
            int r0 = wm * 32 + mb * 16 + gq;
#pragma unroll
            for (int nb = 0; nb < 8; nb++) {
                int col = wn * 64 + nb * 8 + tc2;
                float bv0 = ba[nh * 128 + col], bv1 = ba[nh * 128 + col + 1];
                float z0 = acc[mb][nb][0] + bv0;
                float z1 = acc[mb][nb][1] + bv1;
                float z2 = acc[mb][nb][2] + bv0;
                float z3 = acc[mb][nb][3] + bv1;
                z0 = z0 * (1.0f / (1.0f + __expf(-z0)));
                z1 = z1 * (1.0f / (1.0f + __expf(-z1)));
                z2 = z2 * (1.0f / (1.0f + __expf(-z2)));
                z3 = z3 * (1.0f / (1.0f + __expf(-z3)));
                *reinterpret_cast<uint32_t*>(dsm + OHB +
                    ((uint32_t)r0 * PADH + nh * 128 + col) * 2) =
                    pack_f16x2(z0, z1);
                *reinterpret_cast<uint32_t*>(dsm + OHB +
                    ((uint32_t)(r0 + 8) * PADH + nh * 128 + col) * 2) =
                    pack_f16x2(z2, z3);
            }
        }
    }
    __syncthreads();     // h buffer complete before phase 2

    // ================= phase 2: out = h @ Wb^T + bb ==========================
    for (int n2 = 0; n2 < N2H; n2++) {
        zacc();
        const __half* W2h = Wb + (size_t)n2 * 128 * DD;

        cpB2(W2h, 0, sb + 0 * P2STG); CP_COMMIT();
        cpB2(W2h, 1, sb + 1 * P2STG); CP_COMMIT();
        cpB2(W2h, 2, sb + 2 * P2STG); CP_COMMIT();

#pragma unroll
        for (int kc = 0; kc < NC; kc++) {
            CP_WAIT(2);
            __syncthreads();
            if (kc + 3 < NC) {
                cpB2(W2h, kc + 3, sb + ((kc + 3) & 3) * P2STG); CP_COMMIT();
            } else {
                CP_COMMIT();
            }
            compute2(sb + (kc & 3) * P2STG, kc);
        }
        __syncthreads();

        // epilogue: bias only
#pragma unroll
        for (int mb = 0; mb < 2; mb++) {
            int r0 = mtile + wm * 32 + mb * 16 + gq;
#pragma unroll
            for (int nb = 0; nb < 8; nb++) {
                int col = n2 * 128 + wn * 64 + nb * 8 + tc2;
                float bv0 = bb[col], bv1 = bb[col + 1];
                float z0 = acc[mb][nb][0] + bv0;
                float z1 = acc[mb][nb][1] + bv1;
                float z2 = acc[mb][nb][2] + bv0;
                float z3 = acc[mb][nb][3] + bv1;
                if (SOUT) {
                    *reinterpret_cast<uint32_t*>(&S16[(size_t)r0 * DD + col]) =
                        pack_f16x2(z0, z1);
                    *reinterpret_cast<uint32_t*>(&S16[(size_t)(r0 + 8) * DD + col]) =
                        pack_f16x2(z2, z3);
                } else {
                    *reinterpret_cast<float2*>(&Fout[(size_t)r0 * ldout + col]) =
                        make_float2(z0, z1);
                    *reinterpret_cast<float2*>(&Fout[(size_t)(r0 + 8) * ldout + col]) =
                        make_float2(z2, z3);
                }
            }
        }
    }
}

// ---------------------------------------------------------------------------
// Segment softmax-weighted sum, both s and x fp16, 8-row unroll (no max shift;
// |s| <~ 6 so fp32 exp is safe; softmax shift-invariance => same result)
// ---------------------------------------------------------------------------
__global__ __launch_bounds__(256)
void segment_softmax_kernel(const __half* __restrict__ s16,
                            const __half* __restrict__ x16,
                            const int* __restrict__ offs,
                            float* __restrict__ sx)
{
    int b = blockIdx.x;
    int d = threadIdx.x;
    int start = offs[b], end = offs[b + 1];

    const __half* sp = s16 + (size_t)start * DD + d;
    const __half* xp = x16 + (size_t)start * DD + d;

    float se = 0.0f, sex = 0.0f;
    int i = start;
    for (; i + 7 < end; i += 8) {
        float s0 = __half2float(sp[0]);
        float s1 = __half2float(sp[DD]);
        float s2 = __half2float(sp[2 * DD]);
        float s3 = __half2float(sp[3 * DD]);
        float s4 = __half2float(sp[4 * DD]);
        float s5 = __half2float(sp[5 * DD]);
        float s6 = __half2float(sp[6 * DD]);
        float s7 = __half2float(sp[7 * DD]);
        float x0 = __half2float(xp[0]);
        float x1 = __half2float(xp[DD]);
        float x2 = __half2float(xp[2 * DD]);
        float x3 = __half2float(xp[3 * DD]);
        float x4 = __half2float(xp[4 * DD]);
        float x5 = __half2float(xp[5 * DD]);
        float x6 = __half2float(xp[6 * DD]);
        float x7 = __half2float(xp[7 * DD]);
        sp += 8 * DD; xp += 8 * DD;
        float e0 = __expf(s0), e1 = __expf(s1);
        float e2 = __expf(s2), e3 = __expf(s3);
        float e4 = __expf(s4), e5 = __expf(s5);
        float e6 = __expf(s6), e7 = __expf(s7);
        se  += ((e0 + e1) + (e2 + e3)) + ((e4 + e5) + (e6 + e7));
        sex += ((e0 * x0 + e1 * x1) + (e2 * x2 + e3 * x3)) +
               ((e4 * x4 + e5 * x5) + (e6 * x6 + e7 * x7));
    }
    for (; i < end; i++) {
        float e = __expf(__half2float(sp[0]));
        se  += e;
        sex += e * __half2float(xp[0]);
        sp += DD; xp += DD;
    }
    sx[b * DD + d] = (end > start) ? (sex / se) : 0.0f;
}

// ---------------------------------------------------------------------------
extern "C" void kernel_launch(void* const* d_in, const int* in_sizes, int n_in,
                              void* d_out, int out_size)
{
    const float* x     = (const float*)d_in[0];
    const int*   index = (const int*)  d_in[1];
    const float* W1    = (const float*)d_in[2];
    const float* b1    = (const float*)d_in[3];
    const float* W2    = (const float*)d_in[4];
    const float* b2    = (const float*)d_in[5];
    const float* W3    = (const float*)d_in[6];
    const float* b3    = (const float*)d_in[7];
    const float* W4    = (const float*)d_in[8];
    const float* b4    = (const float*)d_in[9];
    float* out = (float*)d_out;

    float *sx;
    int* offs;
    __half *s16, *x16, *w1t, *w2t, *w3t, *w4t;
    cudaGetSymbolAddress((void**)&s16,  g_s16);
    cudaGetSymbolAddress((void**)&x16,  g_x16);
    cudaGetSymbolAddress((void**)&sx,   g_sx);
    cudaGetSymbolAddress((void**)&offs, g_offs);
    cudaGetSymbolAddress((void**)&w1t,  g_w1t);
    cudaGetSymbolAddress((void**)&w2t,  g_w2t);
    cudaGetSymbolAddress((void**)&w3t,  g_w3t);
    cudaGetSymbolAddress((void**)&w4t,  g_w4t);

    cudaFuncSetAttribute((const void*)fused_mlp<2, true, true>,
                         cudaFuncAttributeMaxDynamicSharedMemorySize, SMEM_FUSED);
    cudaFuncSetAttribute((const void*)fused_mlp<1, false, false>,
                         cudaFuncAttributeMaxDynamicSharedMemorySize, SMEM_FUSED);

    // 0. transpose weights to fp16 [n][k]
    prep_weights_kernel<<<dim3(DD, 4), DD>>>(W1, W2, W3, W4);

    // 1. segment boundaries
    seg_offsets_kernel<<<(SEGS + 1 + 255) / 256, 256>>>(index, offs);

    // 2+3. s = silu(x@W1+b1)@W2 + b2 -> fp16; also writes x16 (side product)
    fused_mlp<2, true, true><<<NN / 128, 256, SMEM_FUSED>>>(
        x, w1t, b1, w2t, b2, s16, nullptr, 0, x16);

    // 4. fused scatter-softmax + weighted segment sum (all-fp16 inputs)
    segment_softmax_kernel<<<SEGS, 256>>>(s16, x16, offs, sx);

    // 5+6. out = silu(sx@W3+b3)@W4 + b4          (fused readout)
    fused_mlp<1, false, false><<<SEGS / 128, 256, SMEM_FUSED>>>(
        sx, w3t, b3, w4t, b4, nullptr, out, DOUT, nullptr);
}

// round 17
// speedup vs baseline: 1.1009x; 1.1009x over previous
#include <cuda_runtime.h>
#include <cuda_fp16.h>
#include <math.h>
#include <stdint.h>

#define NN 262144
#define DD 256
#define DOUT 128
#define SEGS 4096

// ---------------- device scratch (no allocations allowed) -------------------
__device__ __half g_s16[(size_t)NN * DD];   // scores s as fp16
__device__ float g_sx[SEGS * DD];           // segment-weighted sums
__device__ int   g_offs[SEGS + 1];          // segment start offsets
// pre-transposed fp16 weights, layout [n][k] (K contiguous, K=256)
__device__ __half g_w1t[DD * DD], g_w2t[DD * DD];
__device__ __half g_w3t[DD * DD], g_w4t[DOUT * DD];

// ---------------- helpers ---------------------------------------------------
__device__ __forceinline__ uint32_t smem_u32(const void* p) {
    uint32_t a;
    asm("{ .reg .u64 t; cvta.to.shared.u64 t, %1; cvt.u32.u64 %0, t; }"
        : "=r"(a) : "l"(p));
    return a;
}

__device__ __forceinline__ void ldm_x4(uint32_t* r, uint32_t addr) {
    asm volatile("ldmatrix.sync.aligned.m8n8.x4.shared.b16 {%0,%1,%2,%3}, [%4];"
                 : "=r"(r[0]), "=r"(r[1]), "=r"(r[2]), "=r"(r[3]) : "r"(addr));
}

__device__ __forceinline__ void mma16816(float* c, const uint32_t* a,
                                         uint32_t b0, uint32_t b1) {
    asm volatile(
        "mma.sync.aligned.m16n8k16.row.col.f32.f16.f16.f32 "
        "{%0,%1,%2,%3}, {%4,%5,%6,%7}, {%8,%9}, {%0,%1,%2,%3};"
        : "+f"(c[0]), "+f"(c[1]), "+f"(c[2]), "+f"(c[3])
        : "r"(a[0]), "r"(a[1]), "r"(a[2]), "r"(a[3]), "r"(b0), "r"(b1));
}

__device__ __forceinline__ uint32_t pack_f16x2(float x, float y) {
    __half2 h = __floats2half2_rn(x, y);
    return *reinterpret_cast<uint32_t*>(&h);
}

#define CP_ASYNC16(dst, src) \
    asm volatile("cp.async.cg.shared.global [%0], [%1], 16;" \
                 :: "r"(dst), "l"(src) : "memory")
#define CP_COMMIT() asm volatile("cp.async.commit_group;" ::: "memory")
#define CP_WAIT(n)  asm volatile("cp.async.wait_group %0;" :: "n"(n) : "memory")

// ---------------------------------------------------------------------------
// Weight prep: transpose to [n][k] fp16
// ---------------------------------------------------------------------------
__global__ void prep_weights_kernel(const float* __restrict__ W1,
                                    const float* __restrict__ W2,
                                    const float* __restrict__ W3,
                                    const float* __restrict__ W4)
{
    int n = blockIdx.x;
    int k = threadIdx.x;
    int which = blockIdx.y;
    const float* W;
    __half* Wt;
    int ncols;
    if (which == 0)      { W = W1; Wt = g_w1t; ncols = DD; }
    else if (which == 1) { W = W2; Wt = g_w2t; ncols = DD; }
    else if (which == 2) { W = W3; Wt = g_w3t; ncols = DD; }
    else                 { W = W4; Wt = g_w4t; ncols = DOUT; }
    if (n >= ncols) return;
    Wt[n * DD + k] = __float2half_rn(W[k * ncols + n]);
}

__global__ void seg_offsets_kernel(const int* __restrict__ index, int* __restrict__ offs)
{
    int b = blockIdx.x * blockDim.x + threadIdx.x;
    if (b > SEGS) return;
    int lo = 0, hi = NN;
    while (lo < hi) {
        int mid = (lo + hi) >> 1;
        if (index[mid] < b) lo = mid + 1;
        else hi = mid;
    }
    offs[b] = lo;
}

// ---------------------------------------------------------------------------
// Fused 2-layer MLP: out = (silu(A@Wa^T + ba)) @ Wb^T + bb
//  Phase 1: per 128-col half, pipelined fp32->fp16 A + W tiles -> h in SMEM.
//  Phase 2: A = h (smem direct, 264-b16 stride), 4-deep W-only cp.async ring.
// ---------------------------------------------------------------------------
#define NC    8
#define PADK  40
#define PADH  264
#define P1STG 20480
#define P2STG 10240
#define OHB   40960
#define SMEM_FUSED (OHB + 128 * PADH * 2)   // 108544 bytes

template <int N2H, bool SOUT>
__global__ __launch_bounds__(256, 2)
void fused_mlp(const float* __restrict__ A32,
               const __half* __restrict__ Wa,
               const float* __restrict__ ba,
               const __half* __restrict__ Wb,
               const float* __restrict__ bb,
               __half* __restrict__ S16,
               float* __restrict__ Fout, int ldout)
{
    extern __shared__ char dsm[];
    const uint32_t sb = smem_u32(dsm);

    const int tid  = threadIdx.x;
    const int lane = tid & 31;
    const int wid  = tid >> 5;
    const int wm   = wid & 3;
    const int wn   = wid >> 2;
    const int mtile = blockIdx.x * 128;

    const int a_row = (lane & 15);
    const int a_ko  = (lane & 16) ? 8 : 0;
    const int b_row = (lane & 7) + ((lane & 16) ? 8 : 0);
    const int b_ko  = (lane & 8) ? 8 : 0;
    const int gq    = lane >> 2;
    const int tc2   = (lane & 3) * 2;

    float acc[2][8][4];
    float4 ra[4];

    auto zacc = [&] {
#pragma unroll
        for (int i = 0; i < 2; i++)
#pragma unroll
            for (int j = 0; j < 8; j++)
#pragma unroll
                for (int q = 0; q < 4; q++) acc[i][j][q] = 0.0f;
    };
    auto ldgA = [&](int kc) {
        const int k0 = kc * 32;
#pragma unroll
        for (int t = 0; t < 4; t++) {
            int idx = tid + t * 256;
            int r = idx >> 3, c = idx & 7;
            ra[t] = *reinterpret_cast<const float4*>(
                &A32[(size_t)(mtile + r) * DD + k0 + c * 4]);
        }
    };
    auto stcvA = [&](uint32_t stgoff) {
#pragma unroll
        for (int t = 0; t < 4; t++) {
            int idx = tid + t * 256;
            int r = idx >> 3, c = idx & 7;
            float4 v = ra[t];
            uint2 p;
            p.x = pack_f16x2(v.x, v.y);
            p.y = pack_f16x2(v.z, v.w);
            *reinterpret_cast<uint2*>(
                dsm + stgoff + (uint32_t)(r * PADK + c * 4) * 2) = p;
        }
    };
    auto cpB1 = [&](const __half* Wh, int kc, uint32_t stg) {
        const int k0 = kc * 32;
#pragma unroll
        for (int t = 0; t < 2; t++) {
            int idx = tid + t * 256;
            int r = idx >> 2, c = idx & 3;
            CP_ASYNC16(stg + 10240 + (uint32_t)(r * PADK + c * 8) * 2,
                       Wh + (size_t)r * DD + k0 + c * 8);
        }
    };
    auto cpB2 = [&](const __half* Wh, int kc, uint32_t stg) {
        const int k0 = kc * 32;
#pragma unroll
        for (int t = 0; t < 2; t++) {
            int idx = tid + t * 256;
            int r = idx >> 2, c = idx & 3;
            CP_ASYNC16(stg + (uint32_t)(r * PADK + c * 8) * 2,
                       Wh + (size_t)r * DD + k0 + c * 8);
        }
    };
    auto compute1 = [&](uint32_t stg) {
        const uint32_t bA = stg, bB = stg + 10240;
#pragma unroll
        for (int ks = 0; ks < 2; ks++) {
            const int kb = ks * 16;
            uint32_t a[2][4];
#pragma unroll
            for (int mb = 0; mb < 2; mb++) {
                int row = wm * 32 + mb * 16 + a_row;
                ldm_x4(a[mb], bA + (uint32_t)(row * PADK + kb + a_ko) * 2);
            }
#pragma unroll
            for (int g = 0; g < 4; g++) {
                int n = wn * 64 + g * 16 + b_row;
                uint32_t bh[4];
                ldm_x4(bh, bB + (uint32_t)(n * PADK + kb + b_ko) * 2);
#pragma unroll
                for (int mb = 0; mb < 2; mb++)
#pragma unroll
                    for (int nb = 0; nb < 2; nb++)
                        mma16816(acc[mb][g * 2 + nb], a[mb],
                                 bh[nb * 2], bh[nb * 2 + 1]);
            }
        }
    };
    auto compute2 = [&](uint32_t bstg, int kc) {
#pragma unroll
        for (int ks = 0; ks < 2; ks++) {
            const int kb = ks * 16;
            uint32_t a[2][4];
#pragma unroll
            for (int mb = 0; mb < 2; mb++) {
                int row = wm * 32 + mb * 16 + a_row;
                ldm_x4(a[mb], sb + OHB +
                       (uint32_t)(row * PADH + kc * 32 + kb + a_ko) * 2);
            }
#pragma unroll
            for (int g = 0; g < 4; g++) {
                int n = wn * 64 + g * 16 + b_row;
                uint32_t bh[4];
                ldm_x4(bh, bstg + (uint32_t)(n * PADK + kb + b_ko) * 2);
#pragma unroll
                for (int mb = 0; mb < 2; mb++)
#pragma unroll
                    for (int nb = 0; nb < 2; nb++)
                        mma16816(acc[mb][g * 2 + nb], a[mb],
                                 bh[nb * 2], bh[nb * 2 + 1]);
            }
        }
    };

    // ================= phase 1: h = silu(A@Wa^T + ba) -> HBUF ===============
    const uint32_t p1s[2] = {sb, sb + P1STG};
    for (int nh = 0; nh < 2; nh++) {
        zacc();
        const __half* Wh = Wa + (size_t)nh * 128 * DD;

        ldgA(0); stcvA(0);
        cpB1(Wh, 0, p1s[0]); CP_COMMIT();
        ldgA(1);
        CP_WAIT(0);
        __syncthreads();

#pragma unroll
        for (int kc = 0; kc < NC; kc++) {
            const uint32_t cur = p1s[kc & 1];
            const uint32_t nxt = p1s[(kc + 1) & 1];
            if (kc + 1 < NC) {
                stcvA(nxt - sb);
                if (kc + 2 < NC) ldgA(kc + 2);
                cpB1(Wh, kc + 1, nxt); CP_COMMIT();
            }
            compute1(cur);
            CP_WAIT(0);
            __syncthreads();
        }

        // epilogue: silu -> h buffer (fp16, local rows)
#pragma unroll
        for (int mb = 0; mb < 2; mb++) {
            int r0 = wm * 32 + mb * 16 + gq;
#pragma unroll
            for (int nb = 0; nb < 8; nb++) {
                int col = wn * 64 + nb * 8 + tc2;
                float bv0 = ba[nh * 128 + col], bv1 = ba[nh * 128 + col + 1];
                float z0 = acc[mb][nb][0] + bv0;
                float z1 = acc[mb][nb][1] + bv1;
                float z2 = acc[mb][nb][2] + bv0;
                float z3 = acc[mb][nb][3] + bv1;
                z0 = z0 * (1.0f / (1.0f + __expf(-z0)));
                z1 = z1 * (1.0f / (1.0f + __expf(-z1)));
                z2 = z2 * (1.0f / (1.0f + __expf(-z2)));
                z3 = z3 * (1.0f / (1.0f + __expf(-z3)));
                *reinterpret_cast<uint32_t*>(dsm + OHB +
                    ((uint32_t)r0 * PADH + nh * 128 + col) * 2) =
                    pack_f16x2(z0, z1);
                *reinterpret_cast<uint32_t*>(dsm + OHB +
                    ((uint32_t)(r0 + 8) * PADH + nh * 128 + col) * 2) =
                    pack_f16x2(z2, z3);
            }
        }
    }
    __syncthreads();     // h buffer complete before phase 2

    // ================= phase 2: out = h @ Wb^T + bb ==========================
    for (int n2 = 0; n2 < N2H; n2++) {
        zacc();
        const __half* W2h = Wb + (size_t)n2 * 128 * DD;

        cpB2(W2h, 0, sb + 0 * P2STG); CP_COMMIT();
        cpB2(W2h, 1, sb + 1 * P2STG); CP_COMMIT();
        cpB2(W2h, 2, sb + 2 * P2STG); CP_COMMIT();

#pragma unroll
        for (int kc = 0; kc < NC; kc++) {
            CP_WAIT(2);
            __syncthreads();
            if (kc + 3 < NC) {
                cpB2(W2h, kc + 3, sb + ((kc + 3) & 3) * P2STG); CP_COMMIT();
            } else {
                CP_COMMIT();
            }
            compute2(sb + (kc & 3) * P2STG, kc);
        }
        __syncthreads();

        // epilogue: bias only
#pragma unroll
        for (int mb = 0; mb < 2; mb++) {
            int r0 = mtile + wm * 32 + mb * 16 + gq;
#pragma unroll
            for (int nb = 0; nb < 8; nb++) {
                int col = n2 * 128 + wn * 64 + nb * 8 + tc2;
                float bv0 = bb[col], bv1 = bb[col + 1];
                float z0 = acc[mb][nb][0] + bv0;
                float z1 = acc[mb][nb][1] + bv1;
                float z2 = acc[mb][nb][2] + bv0;
                float z3 = acc[mb][nb][3] + bv1;
                if (SOUT) {
                    *reinterpret_cast<uint32_t*>(&S16[(size_t)r0 * DD + col]) =
                        pack_f16x2(z0, z1);
                    *reinterpret_cast<uint32_t*>(&S16[(size_t)(r0 + 8) * DD + col]) =
                        pack_f16x2(z2, z3);
                } else {
                    *reinterpret_cast<float2*>(&Fout[(size_t)r0 * ldout + col]) =
                        make_float2(z0, z1);
                    *reinterpret_cast<float2*>(&Fout[(size_t)(r0 + 8) * ldout + col]) =
                        make_float2(z2, z3);
                }
            }
        }
    }
}

// ---------------------------------------------------------------------------
// Segment softmax-weighted sum: no max shift (|s| <~ 6, fp32 exp safe),
// 8-row unroll with batched loads for MLP.
// ---------------------------------------------------------------------------
__global__ __launch_bounds__(256)
void segment_softmax_kernel(const __half* __restrict__ s16,
                            const float* __restrict__ x,
                            const int* __restrict__ offs,
                            float* __restrict__ sx)
{
    int b = blockIdx.x;
    int d = threadIdx.x;
    int start = offs[b], end = offs[b + 1];

    const __half* sp = s16 + (size_t)start * DD + d;
    const float*  xp = x   + (size_t)start * DD + d;

    float se = 0.0f, sex = 0.0f;
    int i = start;
    for (; i + 7 < end; i += 8) {
        float s0 = __half2float(sp[0]);
        float s1 = __half2float(sp[DD]);
        float s2 = __half2float(sp[2 * DD]);
        float s3 = __half2float(sp[3 * DD]);
        float s4 = __half2float(sp[4 * DD]);
        float s5 = __half2float(sp[5 * DD]);
        float s6 = __half2float(sp[6 * DD]);
        float s7 = __half2float(sp[7 * DD]);
        float x0 = xp[0], x1 = xp[DD], x2 = xp[2 * DD], x3 = xp[3 * DD];
        float x4 = xp[4 * DD], x5 = xp[5 * DD], x6 = xp[6 * DD], x7 = xp[7 * DD];
        sp += 8 * DD; xp += 8 * DD;
        float e0 = __expf(s0), e1 = __expf(s1);
        float e2 = __expf(s2), e3 = __expf(s3);
        float e4 = __expf(s4), e5 = __expf(s5);
        float e6 = __expf(s6), e7 = __expf(s7);
        se  += ((e0 + e1) + (e2 + e3)) + ((e4 + e5) + (e6 + e7));
        sex += ((e0 * x0 + e1 * x1) + (e2 * x2 + e3 * x3)) +
               ((e4 * x4 + e5 * x5) + (e6 * x6 + e7 * x7));
    }
    for (; i < end; i++) {
        float e = __expf(__half2float(sp[0]));
        se  += e;
        sex += e * xp[0];
        sp += DD; xp += DD;
    }
    sx[b * DD + d] = (end > start) ? (sex / se) : 0.0f;
}

// ---------------------------------------------------------------------------
extern "C" void kernel_launch(void* const* d_in, const int* in_sizes, int n_in,
                              void* d_out, int out_size)
{
    const float* x     = (const float*)d_in[0];
    const int*   index = (const int*)  d_in[1];
    const float* W1    = (const float*)d_in[2];
    const float* b1    = (const float*)d_in[3];
    const float* W2    = (const float*)d_in[4];
    const float* b2    = (const float*)d_in[5];
    const float* W3    = (const float*)d_in[6];
    const float* b3    = (const float*)d_in[7];
    const float* W4    = (const float*)d_in[8];
    const float* b4    = (const float*)d_in[9];
    float* out = (float*)d_out;

    float *sx;
    int* offs;
    __half *s16, *w1t, *w2t, *w3t, *w4t;
    cudaGetSymbolAddress((void**)&s16,  g_s16);
    cudaGetSymbolAddress((void**)&sx,   g_sx);
    cudaGetSymbolAddress((void**)&offs, g_offs);
    cudaGetSymbolAddress((void**)&w1t,  g_w1t);
    cudaGetSymbolAddress((void**)&w2t,  g_w2t);
    cudaGetSymbolAddress((void**)&w3t,  g_w3t);
    cudaGetSymbolAddress((void**)&w4t,  g_w4t);

    cudaFuncSetAttribute((const void*)fused_mlp<2, true>,
                         cudaFuncAttributeMaxDynamicSharedMemorySize, SMEM_FUSED);
    cudaFuncSetAttribute((const void*)fused_mlp<1, false>,
                         cudaFuncAttributeMaxDynamicSharedMemorySize, SMEM_FUSED);

    // 0. transpose weights to fp16 [n][k]
    prep_weights_kernel<<<dim3(DD, 4), DD>>>(W1, W2, W3, W4);

    // 1. segment boundaries
    seg_offsets_kernel<<<(SEGS + 1 + 255) / 256, 256>>>(index, offs);

    // 2+3. s = silu(x@W1+b1)@W2 + b2  -> fp16   (fused, h in smem)
    fused_mlp<2, true><<<NN / 128, 256, SMEM_FUSED>>>(
        x, w1t, b1, w2t, b2, s16, nullptr, 0);

    // 4. fused scatter-softmax + weighted segment sum
    segment_softmax_kernel<<<SEGS, 256>>>(s16, x, offs, sx);

    // 5+6. out = silu(sx@W3+b3)@W4 + b4          (fused readout)
    fused_mlp<1, false><<<SEGS / 128, 256, SMEM_FUSED>>>(
        sx, w3t, b3, w4t, b4, nullptr, out, DOUT);
}